// round 15
// baseline (speedup 1.0000x reference)
#include <cuda_runtime.h>

// Problem constants
#define NB    32
#define NH    12
#define GRID  14          // GH == GW
#define LTOK  196         // GRID*GRID
#define DHEAD 64
#define NSTEP 13          // steps 1..13
#define CHUNK 16          // d-chunk per block (DHEAD/4)
#define STR   20          // padded token stride (floats), 16B-aligned, conflict-free
#define TPB   224         // 14 lines x 16 d = 224 tasks, one per thread
#define CSL   (4 * NSTEP * CHUNK)   // 832 coeff floats per (head, d-quarter) slice

// out[b,h,m,d] = x[b,h,m,d]
//   + sum_{dir,step valid} C[h][dir][step][d] * x[b,h,neighbor(m,dir,step),d]
// C[h][dir][step][d] = sd(step)*P[dir*4+si][d][h] + nd(step)*P[dir*4+si+1][d][h],
// P = param_1 + param_2.  Separable: ys = x + V(x) in smem, out = ys + H(x).
//
// Coefficients precomputed by a prep kernel into Cg in PAIR-INTERLEAVED layout
//   Cg[slice][phase][step][d][{fwd,bwd}]  (phase 0 = V: top/bottom, 1 = H: left/right)
// so the conv s-loop does ONE LDS.64 per step (was two scalar LDS), software-
// pipelined one step ahead. Save kernel launched with PDL to hide prep.
//
// Step tables (precomputed, matches reference double-precision build to ~1e-7):
__constant__ float DIST_C[NSTEP] = {
    0.9949110f, 0.9797987f, 0.9551199f, 0.9216104f, 0.8802485f,
    0.8322075f, 0.7788008f, 0.7214223f, 0.6614868f, 0.6003730f,
    0.5393734f, 0.4796523f, 0.4222132f };
__constant__ float FRAC_C[NSTEP] = {
    0.00000000f, 0.23076923f, 0.46153846f, 0.69230769f, 0.92307692f,
    0.15384615f, 0.38461538f, 0.61538462f, 0.84615385f, 0.07692308f,
    0.30769231f, 0.53846154f, 0.76923077f };
__constant__ int SI_C[NSTEP] = { 0,0,0,0,0, 1,1,1,1, 2,2,2,2 };

// Precomputed coefficients: 48 slices x 832 floats, pair-interleaved
__device__ float Cg[NH * 4 * CSL];   // 159744 B, static device buffer (no alloc)

__global__ __launch_bounds__(CSL, 2)
void prep_kernel(const float* __restrict__ p1, const float* __restrict__ p2)
{
    const int slice = blockIdx.x;        // h*4 + dq
    const int hd    = slice >> 2;
    const int dlo   = (slice & 3) * CHUNK;
    const int i     = threadIdx.x;       // 0..831

    // i = ((phase*NSTEP + s)*CHUNK + d)*2 + pr
    int pr    = i & 1;
    int d     = (i >> 1) & (CHUNK - 1);
    int s     = (i >> 5) % NSTEP;
    int phase = i / (NSTEP * CHUNK * 2);
    int dir   = phase * 2 + pr;          // 0:top 1:bottom 2:left 3:right

    int si   = SI_C[s];
    float fr = FRAC_C[s];
    float ds = DIST_C[s];
    int k0   = dir * 4 + si;
    int ia   = (k0 * DHEAD + dlo + d) * NH + hd;
    int ib   = ((k0 + 1) * DHEAD + dlo + d) * NH + hd;
    float pa = p1[ia] + p2[ia];
    float pb = p1[ib] + p2[ib];
    Cg[slice * CSL + i] = ds * (1.0f - fr) * pa + ds * fr * pb;

    // All Cg writes above are visible to dependents after this trigger.
    asm volatile("griddepcontrol.launch_dependents;" ::: "memory");
}

__global__ __launch_bounds__(TPB, 6)   // 48-reg budget: xc/acc register-resident
void save_kernel(const float* __restrict__ x, float* __restrict__ out)
{
    __shared__ float xs[LTOK * STR];             // 15680 B : x tile (padded)
    __shared__ float ys[LTOK * STR];             // 15680 B : x + V(x) (padded)
    __shared__ float Cs[CSL];                    //  3328 B : coeff slice (pairs)

    const int blk = blockIdx.x;       // (b*NH + h) * 4 + dquarter
    const int bh  = blk >> 2;
    const int dlo = (blk & 3) * CHUNK;
    const int hd  = bh % NH;
    const int tid = threadIdx.x;

    const float* xb = x   + (size_t)bh * (LTOK * DHEAD);
    float*       ob = out + (size_t)bh * (LTOK * DHEAD);

    // ---- x tile load: independent of prep, front-runs the PDL wait ----
    #pragma unroll
    for (int it = 0; it < 4; it++) {
        int i = tid + it * TPB;
        if (i < LTOK * (CHUNK / 4)) {
            int row = i >> 2;
            int c4  = i & 3;
            float4 v = *(const float4*)&xb[row * DHEAD + dlo + c4 * 4];
            *(float4*)&xs[row * STR + c4 * 4] = v;
        }
    }

    // ---- wait for prep's Cg, then coalesced coeff-slice load ----
    asm volatile("griddepcontrol.wait;" ::: "memory");
    {
        const float4* cg4 = (const float4*)&Cg[(hd * 4 + (blk & 3)) * CSL];
        if (tid < CSL / 4)
            ((float4*)Cs)[tid] = cg4[tid];
    }
    __syncthreads();

    const int d  = tid & (CHUNK - 1);   // 0..15
    const int g0 = tid >> 4;            // line index 0..13
    const int cb = d * 2;               // coeff pair offset within a step row

    // ===== V phase: ys = x + vertical conv (s-outer, pipelined coeffs) =====
    {
        const int w = g0;

        float xc[GRID], acc[GRID];
        #pragma unroll
        for (int hh = 0; hh < GRID; hh++) {
            xc[hh]  = xs[(hh * GRID + w) * STR + d];
            acc[hh] = xc[hh];
        }
        // phase 0 pairs start at Cs[0]; step row = 32 floats
        float2 cp = *(const float2*)&Cs[0 * 32 + cb];
        #pragma unroll
        for (int s = 1; s <= NSTEP; s++) {
            float2 cn = (s < NSTEP) ? *(const float2*)&Cs[s * 32 + cb]
                                    : make_float2(0.0f, 0.0f);
            #pragma unroll
            for (int hh = s; hh < GRID; hh++)
                acc[hh] = fmaf(cp.x, xc[hh - s], acc[hh]);     // top (h - s)
            #pragma unroll
            for (int hh = 0; hh + s < GRID; hh++)
                acc[hh] = fmaf(cp.y, xc[hh + s], acc[hh]);     // bottom (h + s)
            cp = cn;
        }
        #pragma unroll
        for (int hh = 0; hh < GRID; hh++)
            ys[(hh * GRID + w) * STR + d] = acc[hh];
    }
    __syncthreads();   // ys complete before H-phase reads

    // ===== H phase: out = ys + horizontal conv (single gmem write) =====
    {
        const int hr = g0;

        float xr[GRID], acc[GRID];
        #pragma unroll
        for (int ww = 0; ww < GRID; ww++) {
            xr[ww]  = xs[(hr * GRID + ww) * STR + d];
            acc[ww] = ys[(hr * GRID + ww) * STR + d];   // x + V already in
        }
        // phase 1 pairs start at Cs[NSTEP*32]
        float2 cp = *(const float2*)&Cs[(NSTEP + 0) * 32 + cb];
        #pragma unroll
        for (int s = 1; s <= NSTEP; s++) {
            float2 cn = (s < NSTEP) ? *(const float2*)&Cs[(NSTEP + s) * 32 + cb]
                                    : make_float2(0.0f, 0.0f);
            #pragma unroll
            for (int ww = s; ww < GRID; ww++)
                acc[ww] = fmaf(cp.x, xr[ww - s], acc[ww]);     // left (w - s)
            #pragma unroll
            for (int ww = 0; ww + s < GRID; ww++)
                acc[ww] = fmaf(cp.y, xr[ww + s], acc[ww]);     // right (w + s)
            cp = cn;
        }
        #pragma unroll
        for (int ww = 0; ww < GRID; ww++)
            ob[(hr * GRID + ww) * DHEAD + dlo + d] = acc[ww];
    }
}

extern "C" void kernel_launch(void* const* d_in, const int* in_sizes, int n_in,
                              void* d_out, int out_size)
{
    // metadata order: x, table, param_1, param_2 (table recomputed analytically)
    const float* x  = (const float*)d_in[0];
    const float* p1 = (const float*)d_in[2];
    const float* p2 = (const float*)d_in[3];
    float*       out = (float*)d_out;

    // 1) coefficients -> Cg (pair-interleaved layout)
    prep_kernel<<<NH * 4, CSL>>>(p1, p2);

    // 2) main pass, PDL: begins while prep drains; waits internally for Cg
    cudaLaunchConfig_t cfg = {};
    cfg.gridDim  = dim3(NB * NH * 4);
    cfg.blockDim = dim3(TPB);
    cudaLaunchAttribute attr[1];
    attr[0].id = cudaLaunchAttributeProgrammaticStreamSerialization;
    attr[0].val.programmaticStreamSerializationAllowed = 1;
    cfg.attrs = attr;
    cfg.numAttrs = 1;
    cudaLaunchKernelEx(&cfg, save_kernel, x, out);
}

// round 17
// speedup vs baseline: 1.1811x; 1.1811x over previous
#include <cuda_runtime.h>
#include <cstdint>

// Problem constants
#define NB    32
#define NH    12
#define GRID  14          // GH == GW
#define LTOK  196         // GRID*GRID
#define DHEAD 64
#define NSTEP 13          // steps 1..13
#define CHUNK 32          // d-half per block; threads own d-PAIRS (f32x2)
#define NPAIR 16          // d-pairs per block
#define STR   36          // padded token stride (floats), 16B-aligned
#define TPB   224         // 14 lines x 16 pairs
#define CSL   (4 * NSTEP * CHUNK)   // 1664 coeff floats per (head, d-half) slice

// out[b,h,m,d] = x[b,h,m,d]
//   + sum_{dir,step valid} C[h][dir][step][d] * x[b,h,neighbor(m,dir,step),d]
// C[h][dir][step][d] = sd(step)*P[dir*4+si][d][h] + nd(step)*P[dir*4+si+1][d][h],
// P = param_1 + param_2.  Separable: ys = x + V(x) in smem, out = ys + H(x).
//
// R16: packed fma.rn.f32x2 — each thread owns a d-pair; 64-bit smem/gmem ops
// throughout the hot loops. Coefficients precomputed by prep kernel (dir-major
// [dir][step][d] layout, d contiguous for pair loads); PDL hides prep.
//
// Step tables (precomputed, matches reference double-precision build to ~1e-7):
__constant__ float DIST_C[NSTEP] = {
    0.9949110f, 0.9797987f, 0.9551199f, 0.9216104f, 0.8802485f,
    0.8322075f, 0.7788008f, 0.7214223f, 0.6614868f, 0.6003730f,
    0.5393734f, 0.4796523f, 0.4222132f };
__constant__ float FRAC_C[NSTEP] = {
    0.00000000f, 0.23076923f, 0.46153846f, 0.69230769f, 0.92307692f,
    0.15384615f, 0.38461538f, 0.61538462f, 0.84615385f, 0.07692308f,
    0.30769231f, 0.53846154f, 0.76923077f };
__constant__ int SI_C[NSTEP] = { 0,0,0,0,0, 1,1,1,1, 2,2,2,2 };

typedef unsigned long long u64;

__device__ __forceinline__ u64 ffma2(u64 a, u64 b, u64 c) {
    u64 d;
    asm("fma.rn.f32x2 %0, %1, %2, %3;" : "=l"(d) : "l"(a), "l"(b), "l"(c));
    return d;
}

// Precomputed coefficients: 24 slices (h, d-half) x 1664 floats
__device__ float Cg[NH * 2 * CSL];   // 159744 B, static device buffer (no alloc)

__global__ __launch_bounds__(832, 2)
void prep_kernel(const float* __restrict__ p1, const float* __restrict__ p2)
{
    const int slice = blockIdx.x;        // h*2 + dhalf
    const int hd    = slice >> 1;
    const int dlo   = (slice & 1) * CHUNK;
    const int tid   = threadIdx.x;       // 0..831

    #pragma unroll
    for (int it = 0; it < 2; it++) {
        int i = tid + it * 832;          // i = (dir*NSTEP + s)*CHUNK + d
        int d    = i & (CHUNK - 1);
        int s    = (i >> 5) % NSTEP;
        int dir  = i / (NSTEP * CHUNK);
        int si   = SI_C[s];
        float fr = FRAC_C[s];
        float ds = DIST_C[s];
        int k0   = dir * 4 + si;
        int ia   = (k0 * DHEAD + dlo + d) * NH + hd;
        int ib   = ((k0 + 1) * DHEAD + dlo + d) * NH + hd;
        float pa = p1[ia] + p2[ia];
        float pb = p1[ib] + p2[ib];
        Cg[slice * CSL + i] = ds * (1.0f - fr) * pa + ds * fr * pb;
    }
    // All Cg writes above are visible to dependents after this trigger.
    asm volatile("griddepcontrol.launch_dependents;" ::: "memory");
}

__global__ __launch_bounds__(TPB, 3)   // ~95-reg budget: xc/acc pairs resident
void save_kernel(const float* __restrict__ x, float* __restrict__ out)
{
    __shared__ float xs[LTOK * STR];             // 28224 B : x tile (padded)
    __shared__ float ys[LTOK * STR];             // 28224 B : x + V(x)
    __shared__ float Cs[CSL];                    //  6656 B : coeff slice

    const int blk = blockIdx.x;       // (b*NH + h) * 2 + dhalf
    const int bh  = blk >> 1;
    const int dlo = (blk & 1) * CHUNK;
    const int hd  = bh % NH;
    const int tid = threadIdx.x;

    const float* xb = x   + (size_t)bh * (LTOK * DHEAD);
    float*       ob = out + (size_t)bh * (LTOK * DHEAD);

    // ---- x tile load (independent of prep, front-runs the PDL wait) ----
    // 196 tokens * 8 float4 = 1568 vec loads, 7 per thread
    #pragma unroll
    for (int it = 0; it < 7; it++) {
        int i   = tid + it * TPB;
        int row = i >> 3;
        int c4  = i & 7;
        float4 v = *(const float4*)&xb[row * DHEAD + dlo + c4 * 4];
        *(float4*)&xs[row * STR + c4 * 4] = v;
    }

    // ---- wait for prep's Cg, then coalesced coeff-slice load ----
    asm volatile("griddepcontrol.wait;" ::: "memory");
    {
        const float4* cg4 = (const float4*)&Cg[(hd * 2 + (blk & 1)) * CSL];
        #pragma unroll
        for (int it = 0; it < 2; it++) {
            int i = tid + it * TPB;
            if (i < CSL / 4)
                ((float4*)Cs)[i] = cg4[i];
        }
    }
    __syncthreads();

    const int dp = (tid & (NPAIR - 1)) * 2;   // d-pair base (even)
    const int g0 = tid >> 4;                  // line index 0..13

    // ===== V phase: ys = x + vertical conv, packed f32x2 =====
    {
        const int w = g0;

        u64 xc[GRID], acc[GRID];
        #pragma unroll
        for (int hh = 0; hh < GRID; hh++) {
            xc[hh]  = *(const u64*)&xs[(hh * GRID + w) * STR + dp];
            acc[hh] = xc[hh];
        }
        u64 c0 = *(const u64*)&Cs[(0 * NSTEP + 0) * CHUNK + dp];
        u64 c1 = *(const u64*)&Cs[(1 * NSTEP + 0) * CHUNK + dp];
        #pragma unroll
        for (int s = 1; s <= NSTEP; s++) {
            u64 n0 = 0, n1 = 0;
            if (s < NSTEP) {
                n0 = *(const u64*)&Cs[(0 * NSTEP + s) * CHUNK + dp];
                n1 = *(const u64*)&Cs[(1 * NSTEP + s) * CHUNK + dp];
            }
            #pragma unroll
            for (int hh = s; hh < GRID; hh++)
                acc[hh] = ffma2(c0, xc[hh - s], acc[hh]);      // top (h - s)
            #pragma unroll
            for (int hh = 0; hh + s < GRID; hh++)
                acc[hh] = ffma2(c1, xc[hh + s], acc[hh]);      // bottom (h + s)
            c0 = n0; c1 = n1;
        }
        #pragma unroll
        for (int hh = 0; hh < GRID; hh++)
            *(u64*)&ys[(hh * GRID + w) * STR + dp] = acc[hh];
    }
    __syncthreads();   // ys complete before H-phase reads

    // ===== H phase: out = ys + horizontal conv (single gmem write) =====
    {
        const int hr = g0;

        u64 xr[GRID], acc[GRID];
        #pragma unroll
        for (int ww = 0; ww < GRID; ww++) {
            xr[ww]  = *(const u64*)&xs[(hr * GRID + ww) * STR + dp];
            acc[ww] = *(const u64*)&ys[(hr * GRID + ww) * STR + dp]; // x + V in
        }
        u64 c2 = *(const u64*)&Cs[(2 * NSTEP + 0) * CHUNK + dp];
        u64 c3 = *(const u64*)&Cs[(3 * NSTEP + 0) * CHUNK + dp];
        #pragma unroll
        for (int s = 1; s <= NSTEP; s++) {
            u64 n2 = 0, n3 = 0;
            if (s < NSTEP) {
                n2 = *(const u64*)&Cs[(2 * NSTEP + s) * CHUNK + dp];
                n3 = *(const u64*)&Cs[(3 * NSTEP + s) * CHUNK + dp];
            }
            #pragma unroll
            for (int ww = s; ww < GRID; ww++)
                acc[ww] = ffma2(c2, xr[ww - s], acc[ww]);      // left (w - s)
            #pragma unroll
            for (int ww = 0; ww + s < GRID; ww++)
                acc[ww] = ffma2(c3, xr[ww + s], acc[ww]);      // right (w + s)
            c2 = n2; c3 = n3;
        }
        #pragma unroll
        for (int ww = 0; ww < GRID; ww++)
            *(u64*)&ob[(hr * GRID + ww) * DHEAD + dlo + dp] = acc[ww];
    }
}

extern "C" void kernel_launch(void* const* d_in, const int* in_sizes, int n_in,
                              void* d_out, int out_size)
{
    // metadata order: x, table, param_1, param_2 (table recomputed analytically)
    const float* x  = (const float*)d_in[0];
    const float* p1 = (const float*)d_in[2];
    const float* p2 = (const float*)d_in[3];
    float*       out = (float*)d_out;

    // 1) coefficients -> Cg ([dir][step][d] per (head, d-half) slice)
    prep_kernel<<<NH * 2, 832>>>(p1, p2);

    // 2) main pass, PDL: begins while prep drains; waits internally for Cg
    cudaLaunchConfig_t cfg = {};
    cfg.gridDim  = dim3(NB * NH * 2);
    cfg.blockDim = dim3(TPB);
    cudaLaunchAttribute attr[1];
    attr[0].id = cudaLaunchAttributeProgrammaticStreamSerialization;
    attr[0].val.programmaticStreamSerializationAllowed = 1;
    cfg.attrs = attr;
    cfg.numAttrs = 1;
    cudaLaunchKernelEx(&cfg, save_kernel, x, out);
}